// round 13
// baseline (speedup 1.0000x reference)
#include <cuda_runtime.h>
#include <math.h>
#include <stdint.h>

// ---------------- problem constants ----------------
#define BATCH 2
#define SEQ   1024
#define T     2048            // BATCH*SEQ tokens
#define DMODEL 1024
#define NHEAD 16
#define NKV   4
#define HDIM  64
#define NLAYER 4
#define NEXP  8
#define FDIM  1024
#define VOCAB 32000
#define MOE_ROWS (2*T + 128)   // padded for unguarded 128-row tile loads

// ---------------- scratch (device globals; no allocs allowed) ----------------
__device__ float g_x [T*DMODEL];
__device__ float g_h [T*DMODEL];
__device__ float g_q [T*NHEAD*HDIM];
__device__ float g_k [T*NKV*HDIM];
__device__ float g_v [T*NKV*HDIM];
__device__ float g_ao[T*NHEAD*HDIM];
__device__ int   g_topi[T*2];
__device__ float g_gate[T*2];
__device__ int   g_cnt[NEXP];
__device__ int   g_off[NEXP+1];
__device__ int   g_cur[NEXP];
__device__ int   g_ptok[T*2];
__device__ int   g_rowof[T*2];
__device__ float g_hg[(size_t)MOE_ROWS*DMODEL];
__device__ float g_gb[(size_t)MOE_ROWS*FDIM];
__device__ float g_ub[(size_t)MOE_ROWS*FDIM];
__device__ float g_yb[(size_t)MOE_ROWS*DMODEL];

// ---------------- embed ----------------
__global__ void embed_k(const int* __restrict__ ids, const float* __restrict__ emb) {
    int t = blockIdx.x;
    int id = ids[t];
    for (int d = threadIdx.x; d < DMODEL; d += 256)
        g_x[(size_t)t*DMODEL + d] = emb[(size_t)id*DMODEL + d];
}

// ---------------- rmsnorm over DMODEL ----------------
__global__ void rmsnorm_k(const float* __restrict__ in, const float* __restrict__ w,
                          float* __restrict__ out) {
    int t = blockIdx.x, tid = threadIdx.x;
    __shared__ float red[256];
    float s = 0.f;
    for (int d = tid; d < DMODEL; d += 256) { float v = in[(size_t)t*DMODEL + d]; s += v*v; }
    red[tid] = s; __syncthreads();
    for (int off = 128; off > 0; off >>= 1) { if (tid < off) red[tid] += red[tid+off]; __syncthreads(); }
    float r = rsqrtf(red[0]/(float)DMODEL + 1e-6f);
    for (int d = tid; d < DMODEL; d += 256)
        out[(size_t)t*DMODEL + d] = in[(size_t)t*DMODEL + d] * r * w[d];
}

// ---------------- generic tiled SGEMM (R2 verbatim): C = A@B (+res) ----------------
#define BM 64
#define BN 64
#define BK 16
__global__ void sgemm_nn(const float* __restrict__ A, const float* __restrict__ B,
                         float* __restrict__ C, const float* __restrict__ Crs,
                         int M, int N, int K) {
    __shared__ float As[BK][BM+1];
    __shared__ float Bs[BK][BN+1];
    const int n0 = blockIdx.x*BN, m0 = blockIdx.y*BM;
    const int tid = threadIdx.x;
    const int tx = tid & 15, ty = tid >> 4;
    float acc[4][4] = {};
    for (int k0 = 0; k0 < K; k0 += BK) {
#pragma unroll
        for (int i = 0; i < 4; i++) {
            int idx = tid + i*256;
            int m = idx >> 4, kk = idx & 15;
            As[kk][m] = A[(size_t)(m0+m)*K + k0 + kk];
        }
#pragma unroll
        for (int i = 0; i < 4; i++) {
            int idx = tid + i*256;
            int kk = idx >> 6, n = idx & 63;
            Bs[kk][n] = B[(size_t)(k0+kk)*N + n0 + n];
        }
        __syncthreads();
#pragma unroll
        for (int kk = 0; kk < BK; kk++) {
            float a[4], b[4];
#pragma unroll
            for (int i = 0; i < 4; i++) a[i] = As[kk][ty*4+i];
#pragma unroll
            for (int j = 0; j < 4; j++) b[j] = Bs[kk][tx*4+j];
#pragma unroll
            for (int i = 0; i < 4; i++)
#pragma unroll
                for (int j = 0; j < 4; j++) acc[i][j] += a[i]*b[j];
        }
        __syncthreads();
    }
#pragma unroll
    for (int i = 0; i < 4; i++) {
        int row = m0 + ty*4 + i;
#pragma unroll
        for (int j = 0; j < 4; j++) {
            int col = n0 + tx*4 + j;
            float v = acc[i][j];
            if (Crs) v += Crs[(size_t)row*N + col];
            C[(size_t)row*N + col] = v;
        }
    }
}

// B transposed variant (R2 verbatim): C = A @ Bt^T, Bt is [N,K] row-major
__global__ void sgemm_nt(const float* __restrict__ A, const float* __restrict__ Bt,
                         float* __restrict__ C, int M, int N, int K) {
    __shared__ float As[BK][BM+1];
    __shared__ float Bs[BK][BN+1];
    const int n0 = blockIdx.x*BN, m0 = blockIdx.y*BM;
    const int tid = threadIdx.x;
    const int tx = tid & 15, ty = tid >> 4;
    float acc[4][4] = {};
    for (int k0 = 0; k0 < K; k0 += BK) {
#pragma unroll
        for (int i = 0; i < 4; i++) {
            int idx = tid + i*256;
            int m = idx >> 4, kk = idx & 15;
            As[kk][m] = A[(size_t)(m0+m)*K + k0 + kk];
        }
#pragma unroll
        for (int i = 0; i < 4; i++) {
            int idx = tid + i*256;
            int kk = idx & 15, n = idx >> 4;
            Bs[kk][n] = Bt[(size_t)(n0+n)*K + k0 + kk];
        }
        __syncthreads();
#pragma unroll
        for (int kk = 0; kk < BK; kk++) {
            float a[4], b[4];
#pragma unroll
            for (int i = 0; i < 4; i++) a[i] = As[kk][ty*4+i];
#pragma unroll
            for (int j = 0; j < 4; j++) b[j] = Bs[kk][tx*4+j];
#pragma unroll
            for (int i = 0; i < 4; i++)
#pragma unroll
                for (int j = 0; j < 4; j++) acc[i][j] += a[i]*b[j];
        }
        __syncthreads();
    }
#pragma unroll
    for (int i = 0; i < 4; i++) {
        int row = m0 + ty*4 + i;
#pragma unroll
        for (int j = 0; j < 4; j++)
            C[(size_t)row*N + n0 + tx*4 + j] = acc[i][j];
    }
}

// ---- NEW this round: 128x128/BK=8 grouped MoE GEMM, R2 code shape ----
// A=[MOE_ROWS,K] abs-indexed (padded >=128 rows beyond any r1), Ball=[E,K,N].
// Scalar loads/stores only, same two-sync structure as sgemm_moe in R2.
__global__ void sgemm_moe128(const float* __restrict__ A, const float* __restrict__ Ball,
                             float* __restrict__ C, int N, int K) {
    const int e = blockIdx.z;
    const int r0 = g_off[e], r1 = g_off[e+1];
    const int m0 = r0 + blockIdx.y*128;
    if (m0 >= r1) return;
    const float* B = Ball + (size_t)e*K*N;
    __shared__ float As[8][128+1];
    __shared__ float Bs[8][128+1];
    const int n0 = blockIdx.x*128;
    const int tid = threadIdx.x;
    const int tx = tid & 15, ty = tid >> 4;
    float acc[8][8] = {};
    for (int k0 = 0; k0 < K; k0 += 8) {
        // A tile: 128 rows x 8 k  (idx>>3 = m, idx&7 = kk)
#pragma unroll
        for (int i = 0; i < 4; i++) {
            int idx = tid + i*256;
            int m = idx >> 3, kk = idx & 7;
            As[kk][m] = A[(size_t)(m0+m)*K + k0 + kk];   // padded buffer: safe
        }
        // B tile: 8 k x 128 n  (idx>>7 = kk, idx&127 = n)
#pragma unroll
        for (int i = 0; i < 4; i++) {
            int idx = tid + i*256;
            int kk = idx >> 7, n = idx & 127;
            Bs[kk][n] = B[(size_t)(k0+kk)*N + n0 + n];
        }
        __syncthreads();
#pragma unroll
        for (int kk = 0; kk < 8; kk++) {
            float a[8], b[8];
#pragma unroll
            for (int i = 0; i < 8; i++) a[i] = As[kk][ty*8+i];
#pragma unroll
            for (int j = 0; j < 8; j++) b[j] = Bs[kk][tx*8+j];
#pragma unroll
            for (int i = 0; i < 8; i++)
#pragma unroll
                for (int j = 0; j < 8; j++) acc[i][j] += a[i]*b[j];
        }
        __syncthreads();
    }
#pragma unroll
    for (int i = 0; i < 8; i++) {
        int row = m0 + ty*8 + i;
        if (row < r1) {
#pragma unroll
            for (int j = 0; j < 8; j++)
                C[(size_t)row*N + n0 + tx*8 + j] = acc[i][j];
        }
    }
}

// ---------------- per-head rmsnorm + RoPE (R2 verbatim) ----------------
__global__ void qknorm_rope_k(float* __restrict__ x, const float* __restrict__ w,
                              const int* __restrict__ pos, int nh) {
    int t = blockIdx.x, tid = threadIdx.x;
    int hh = tid >> 6, d = tid & 63;
    __shared__ float sh[NHEAD*HDIM];
    float v = x[(size_t)t*nh*HDIM + tid];
    sh[tid] = v*v; __syncthreads();
    for (int off = 32; off > 0; off >>= 1) { if (d < off) sh[tid] += sh[tid+off]; __syncthreads(); }
    float r = rsqrtf(sh[hh*64]/64.0f + 1e-6f);
    __syncthreads();
    float nv = v * r * w[d];
    sh[tid] = nv; __syncthreads();
    float other = (d < 32) ? -sh[hh*64 + d + 32] : sh[hh*64 + d - 32];
    int i = d & 31;
    double invf = exp(-((double)i/32.0) * 13.815510557964274);  // ln(1e6)
    float ang = (float)((double)pos[t] * invf);
    float sv, cv;
    sincosf(ang, &sv, &cv);
    x[(size_t)t*nh*HDIM + tid] = nv*cv + other*sv;
}

// ---------------- attention (R2 verbatim: 128 threads) ----------------
__global__ void attn_k() {
    const int qpos = blockIdx.x, h = blockIdx.y, b = blockIdx.z;
    const int tid = threadIdx.x;
    const int kvh = h >> 2;                 // GQA: 4 q-heads per kv head
    const int t = b*SEQ + qpos;
    __shared__ float qv[HDIM];
    __shared__ float sc[SEQ];
    __shared__ float red[128];
    if (tid < HDIM) qv[tid] = g_q[(size_t)t*(NHEAD*HDIM) + h*HDIM + tid];
    __syncthreads();
    const int nk = qpos + 1;
    float lm = -1e30f;
    for (int j = tid; j < nk; j += 128) {
        const float* kp = g_k + ((size_t)(b*SEQ + j)*NKV + kvh)*HDIM;
        float s = 0.f;
#pragma unroll
        for (int dd = 0; dd < HDIM; dd++) s += qv[dd]*kp[dd];
        s *= 0.125f;                        // 1/sqrt(64)
        sc[j] = s;
        lm = fmaxf(lm, s);
    }
    red[tid] = lm; __syncthreads();
    for (int off = 64; off > 0; off >>= 1) { if (tid < off) red[tid] = fmaxf(red[tid], red[tid+off]); __syncthreads(); }
    float m = red[0]; __syncthreads();
    float ls = 0.f;
    for (int j = tid; j < nk; j += 128) { float p = __expf(sc[j] - m); sc[j] = p; ls += p; }
    red[tid] = ls; __syncthreads();
    for (int off = 64; off > 0; off >>= 1) { if (tid < off) red[tid] += red[tid+off]; __syncthreads(); }
    float inv = 1.0f / red[0];
    if (tid < HDIM) {
        float acc = 0.f;
        for (int j = 0; j < nk; j++)
            acc += sc[j] * g_v[((size_t)(b*SEQ + j)*NKV + kvh)*HDIM + tid];
        g_ao[(size_t)t*(NHEAD*HDIM) + h*HDIM + tid] = acc * inv;
    }
}

// ---------------- router (R2 verbatim) ----------------
__global__ void router_k(const float* __restrict__ rw) {
    int t = blockIdx.x, tid = threadIdx.x;
    float acc[NEXP] = {};
    for (int d = tid; d < DMODEL; d += 256) {
        float hv = g_h[(size_t)t*DMODEL + d];
        const float* rp = rw + (size_t)d*NEXP;
#pragma unroll
        for (int e = 0; e < NEXP; e++) acc[e] += hv*rp[e];
    }
    __shared__ float red[256];
    __shared__ float logits[NEXP];
    for (int e = 0; e < NEXP; e++) {
        red[tid] = acc[e]; __syncthreads();
        for (int off = 128; off > 0; off >>= 1) { if (tid < off) red[tid] += red[tid+off]; __syncthreads(); }
        if (tid == 0) logits[e] = red[0];
        __syncthreads();
    }
    if (tid == 0) {
        float mx = logits[0];
        for (int e = 1; e < NEXP; e++) mx = fmaxf(mx, logits[e]);
        float p[NEXP];
        for (int e = 0; e < NEXP; e++) p[e] = expf(logits[e] - mx);
        int i0 = 0;
        for (int e = 1; e < NEXP; e++) if (p[e] > p[i0]) i0 = e;   // ties -> lowest idx
        int i1 = (i0 == 0) ? 1 : 0;
        for (int e = 0; e < NEXP; e++) if (e != i0 && p[e] > p[i1]) i1 = e;
        float v0 = p[i0], v1 = p[i1], tt = v0 + v1;
        g_topi[t*2] = i0;  g_topi[t*2+1] = i1;
        g_gate[t*2] = v0/tt; g_gate[t*2+1] = v1/tt;
    }
}

// ---------------- routing bookkeeping (R2 verbatim) ----------------
__global__ void route_zero_k()   { if (threadIdx.x < NEXP) g_cnt[threadIdx.x] = 0; }
__global__ void route_count_k()  { int i = blockIdx.x*256 + threadIdx.x; if (i < 2*T) atomicAdd(&g_cnt[g_topi[i]], 1); }
__global__ void route_prefix_k() {
    if (threadIdx.x == 0) {
        int s = 0;
        for (int e = 0; e < NEXP; e++) { g_off[e] = s; g_cur[e] = s; s += g_cnt[e]; }
        g_off[NEXP] = s;
    }
}
__global__ void route_assign_k() {
    int i = blockIdx.x*256 + threadIdx.x;
    if (i < 2*T) {
        int e = g_topi[i];
        int pos = atomicAdd(&g_cur[e], 1);
        g_ptok[pos] = i >> 1;
        g_rowof[i] = pos;
    }
}
__global__ void moe_gather_k() {
    int i = blockIdx.x;
    int tk = g_ptok[i];
    for (int d = threadIdx.x; d < DMODEL; d += 256)
        g_hg[(size_t)i*DMODEL + d] = g_h[(size_t)tk*DMODEL + d];
}
__global__ void moe_act_k() {
    size_t i = (size_t)blockIdx.x*256 + threadIdx.x;   // grid covers 2*T*FDIM
    float g = g_gb[i], u = g_ub[i];
    float sg = g / (1.0f + expf(-g));
    g_gb[i] = sg * u;
}
__global__ void moe_combine_k() {
    int t = blockIdx.x;
    int r0 = g_rowof[t*2], r1 = g_rowof[t*2+1];
    float w0 = g_gate[t*2], w1 = g_gate[t*2+1];
    for (int d = threadIdx.x; d < DMODEL; d += 256)
        g_x[(size_t)t*DMODEL + d] += w0*g_yb[(size_t)r0*DMODEL + d]
                                   + w1*g_yb[(size_t)r1*DMODEL + d];
}

// ---------------- host orchestration ----------------
extern "C" void kernel_launch(void* const* d_in, const int* in_sizes, int n_in,
                              void* d_out, int out_size) {
    const int*   token_ids    = (const int*)  d_in[0];
    const int*   position_ids = (const int*)  d_in[1];
    const float* tok_emb      = (const float*)d_in[2];
    const float* attn_norm_w  = (const float*)d_in[3];
    const float* wq           = (const float*)d_in[4];
    const float* wk           = (const float*)d_in[5];
    const float* wv           = (const float*)d_in[6];
    const float* q_norm_w     = (const float*)d_in[7];
    const float* k_norm_w     = (const float*)d_in[8];
    const float* wo           = (const float*)d_in[9];
    const float* ffn_norm_w   = (const float*)d_in[10];
    const float* router_w     = (const float*)d_in[11];
    const float* gate_w       = (const float*)d_in[12];
    const float* up_w         = (const float*)d_in[13];
    const float* down_w       = (const float*)d_in[14];
    const float* final_norm_w = (const float*)d_in[15];
    float* out = (float*)d_out;

    float* px; cudaGetSymbolAddress((void**)&px, g_x);
    float* ph; cudaGetSymbolAddress((void**)&ph, g_h);
    float* pq; cudaGetSymbolAddress((void**)&pq, g_q);
    float* pk; cudaGetSymbolAddress((void**)&pk, g_k);
    float* pv; cudaGetSymbolAddress((void**)&pv, g_v);
    float* pao; cudaGetSymbolAddress((void**)&pao, g_ao);
    float* phg; cudaGetSymbolAddress((void**)&phg, g_hg);
    float* pgb; cudaGetSymbolAddress((void**)&pgb, g_gb);
    float* pub; cudaGetSymbolAddress((void**)&pub, g_ub);
    float* pyb; cudaGetSymbolAddress((void**)&pyb, g_yb);

    embed_k<<<T, 256>>>(token_ids, tok_emb);

    for (int l = 0; l < NLAYER; l++) {
        const float* wq_l = wq + (size_t)l*DMODEL*(NHEAD*HDIM);
        const float* wk_l = wk + (size_t)l*DMODEL*(NKV*HDIM);
        const float* wv_l = wv + (size_t)l*DMODEL*(NKV*HDIM);
        const float* wo_l = wo + (size_t)l*(NHEAD*HDIM)*DMODEL;
        const float* gw_l = gate_w + (size_t)l*NEXP*DMODEL*FDIM;
        const float* uw_l = up_w   + (size_t)l*NEXP*DMODEL*FDIM;
        const float* dw_l = down_w + (size_t)l*NEXP*FDIM*DMODEL;

        // attention block (R2 verbatim)
        rmsnorm_k<<<T, 256>>>(px, attn_norm_w + (size_t)l*DMODEL, ph);
        sgemm_nn<<<dim3((NHEAD*HDIM)/BN, T/BM), 256>>>(ph, wq_l, pq, nullptr, T, NHEAD*HDIM, DMODEL);
        sgemm_nn<<<dim3((NKV*HDIM)/BN,  T/BM), 256>>>(ph, wk_l, pk, nullptr, T, NKV*HDIM, DMODEL);
        sgemm_nn<<<dim3((NKV*HDIM)/BN,  T/BM), 256>>>(ph, wv_l, pv, nullptr, T, NKV*HDIM, DMODEL);
        qknorm_rope_k<<<T, NHEAD*HDIM>>>(pq, q_norm_w + (size_t)l*HDIM, position_ids, NHEAD);
        qknorm_rope_k<<<T, NKV*HDIM>>>(pk, k_norm_w + (size_t)l*HDIM, position_ids, NKV);
        attn_k<<<dim3(SEQ, NHEAD, BATCH), 128>>>();
        sgemm_nn<<<dim3(DMODEL/BN, T/BM), 256>>>(pao, wo_l, px, px, T, DMODEL, NHEAD*HDIM);

        // MoE block (R2 verbatim except the three GEMMs use sgemm_moe128)
        rmsnorm_k<<<T, 256>>>(px, ffn_norm_w + (size_t)l*DMODEL, ph);
        router_k<<<T, 256>>>(router_w + (size_t)l*DMODEL*NEXP);
        route_zero_k<<<1, 32>>>();
        route_count_k<<<(2*T)/256, 256>>>();
        route_prefix_k<<<1, 32>>>();
        route_assign_k<<<(2*T)/256, 256>>>();
        moe_gather_k<<<2*T, 256>>>();
        sgemm_moe128<<<dim3(FDIM/128, (2*T)/128, NEXP), 256>>>(phg, gw_l, pgb, FDIM, DMODEL);
        sgemm_moe128<<<dim3(FDIM/128, (2*T)/128, NEXP), 256>>>(phg, uw_l, pub, FDIM, DMODEL);
        moe_act_k<<<(2*T*FDIM)/256, 256>>>();
        sgemm_moe128<<<dim3(DMODEL/128, (2*T)/128, NEXP), 256>>>(pgb, dw_l, pyb, DMODEL, FDIM);
        moe_combine_k<<<T, 256>>>();
    }

    // final norm + tied lm_head (R2 verbatim)
    rmsnorm_k<<<T, 256>>>(px, final_norm_w, ph);
    sgemm_nt<<<dim3(VOCAB/BN, T/BM), 256>>>(ph, tok_emb, out, T, VOCAB, DMODEL);
}

// round 16
// speedup vs baseline: 1.2400x; 1.2400x over previous
#include <cuda_runtime.h>
#include <math.h>
#include <stdint.h>

// ---------------- problem constants ----------------
#define BATCH 2
#define SEQ   1024
#define T     2048            // BATCH*SEQ tokens
#define DMODEL 1024
#define NHEAD 16
#define NKV   4
#define HDIM  64
#define NLAYER 4
#define NEXP  8
#define FDIM  1024
#define VOCAB 32000
#define MOE_ROWS (2*T + 128)   // padded for unguarded 128-row tile loads

// ---------------- scratch (device globals; no allocs allowed) ----------------
__device__ float g_x [T*DMODEL];
__device__ float g_h [T*DMODEL];
__device__ float g_q [T*NHEAD*HDIM];
__device__ float g_k [T*NKV*HDIM];
__device__ float g_v [T*NKV*HDIM];
__device__ float g_ao[T*NHEAD*HDIM];
__device__ int   g_topi[T*2];
__device__ float g_gate[T*2];
__device__ int   g_cnt[NEXP];
__device__ int   g_off[NEXP+1];
__device__ int   g_cur[NEXP];
__device__ int   g_ptok[T*2];
__device__ int   g_rowof[T*2];
__device__ float g_hg[(size_t)MOE_ROWS*DMODEL];
__device__ float g_gb[(size_t)MOE_ROWS*FDIM];
__device__ float g_ub[(size_t)MOE_ROWS*FDIM];
__device__ float g_yb[(size_t)MOE_ROWS*DMODEL];

// ---------------- embed ----------------
__global__ void embed_k(const int* __restrict__ ids, const float* __restrict__ emb) {
    int t = blockIdx.x;
    int id = ids[t];
    for (int d = threadIdx.x; d < DMODEL; d += 256)
        g_x[(size_t)t*DMODEL + d] = emb[(size_t)id*DMODEL + d];
}

// ---------------- rmsnorm over DMODEL ----------------
__global__ void rmsnorm_k(const float* __restrict__ in, const float* __restrict__ w,
                          float* __restrict__ out) {
    int t = blockIdx.x, tid = threadIdx.x;
    __shared__ float red[256];
    float s = 0.f;
    for (int d = tid; d < DMODEL; d += 256) { float v = in[(size_t)t*DMODEL + d]; s += v*v; }
    red[tid] = s; __syncthreads();
    for (int off = 128; off > 0; off >>= 1) { if (tid < off) red[tid] += red[tid+off]; __syncthreads(); }
    float r = rsqrtf(red[0]/(float)DMODEL + 1e-6f);
    for (int d = tid; d < DMODEL; d += 256)
        out[(size_t)t*DMODEL + d] = in[(size_t)t*DMODEL + d] * r * w[d];
}

// ---------------- generic tiled SGEMM (R2 verbatim): C = A@B (+res) ----------------
#define BM 64
#define BN 64
#define BK 16
__global__ void sgemm_nn(const float* __restrict__ A, const float* __restrict__ B,
                         float* __restrict__ C, const float* __restrict__ Crs,
                         int M, int N, int K) {
    __shared__ float As[BK][BM+1];
    __shared__ float Bs[BK][BN+1];
    const int n0 = blockIdx.x*BN, m0 = blockIdx.y*BM;
    const int tid = threadIdx.x;
    const int tx = tid & 15, ty = tid >> 4;
    float acc[4][4] = {};
    for (int k0 = 0; k0 < K; k0 += BK) {
#pragma unroll
        for (int i = 0; i < 4; i++) {
            int idx = tid + i*256;
            int m = idx >> 4, kk = idx & 15;
            As[kk][m] = A[(size_t)(m0+m)*K + k0 + kk];
        }
#pragma unroll
        for (int i = 0; i < 4; i++) {
            int idx = tid + i*256;
            int kk = idx >> 6, n = idx & 63;
            Bs[kk][n] = B[(size_t)(k0+kk)*N + n0 + n];
        }
        __syncthreads();
#pragma unroll
        for (int kk = 0; kk < BK; kk++) {
            float a[4], b[4];
#pragma unroll
            for (int i = 0; i < 4; i++) a[i] = As[kk][ty*4+i];
#pragma unroll
            for (int j = 0; j < 4; j++) b[j] = Bs[kk][tx*4+j];
#pragma unroll
            for (int i = 0; i < 4; i++)
#pragma unroll
                for (int j = 0; j < 4; j++) acc[i][j] += a[i]*b[j];
        }
        __syncthreads();
    }
#pragma unroll
    for (int i = 0; i < 4; i++) {
        int row = m0 + ty*4 + i;
#pragma unroll
        for (int j = 0; j < 4; j++) {
            int col = n0 + tx*4 + j;
            float v = acc[i][j];
            if (Crs) v += Crs[(size_t)row*N + col];
            C[(size_t)row*N + col] = v;
        }
    }
}

// ============ tf32 mma.sync helpers (3xTF32 error-compensated) ============
__device__ __forceinline__ void f2tf2(float f, uint32_t& b, uint32_t& s) {
    asm("cvt.rna.tf32.f32 %0, %1;" : "=r"(b) : "f"(f));
    float r = f - __uint_as_float(b);
    asm("cvt.rna.tf32.f32 %0, %1;" : "=r"(s) : "f"(r));
}
__device__ __forceinline__ void mma1688(float* d, const uint32_t* a, const uint32_t* b) {
    asm volatile(
        "mma.sync.aligned.m16n8k8.row.col.f32.tf32.tf32.f32 "
        "{%0,%1,%2,%3}, {%4,%5,%6,%7}, {%8,%9}, {%0,%1,%2,%3};"
        : "+f"(d[0]), "+f"(d[1]), "+f"(d[2]), "+f"(d[3])
        : "r"(a[0]), "r"(a[1]), "r"(a[2]), "r"(a[3]), "r"(b[0]), "r"(b[1]));
}

// ============ lm_head GEMM via 3xTF32 MMA ============
// C[M,N] = A[M,K] @ Bt[N,K]^T.  128x128 tile, BK=32, 256 thr (8 warps),
// warp = 64x32 (4 m16 x 4 n8 mma tiles).  M%128==0, N%128==0, K%32==0.
__global__ void gemm_nt_mma(const float* __restrict__ A, const float* __restrict__ Bt,
                            float* __restrict__ C, int M, int N, int K) {
    __shared__ float As[128][36];   // [m][k]
    __shared__ float Bs[128][36];   // [n][k]
    const int tid = threadIdx.x, lane = tid & 31, warp = tid >> 5;
    const int wr = warp & 1, wc = warp >> 1;     // 2x4 warp grid
    const int m0 = blockIdx.y*128, n0 = blockIdx.x*128;
    const int r = tid >> 3, c = (tid & 7)*4;     // loader coords
    float acc[4][4][4] = {};

    for (int k0 = 0; k0 < K; k0 += 32) {
#pragma unroll
        for (int i = 0; i < 4; i++) {
            float4 va = *reinterpret_cast<const float4*>(&A[(size_t)(m0 + r + i*32)*K + k0 + c]);
            *reinterpret_cast<float4*>(&As[r + i*32][c]) = va;
            float4 vb = *reinterpret_cast<const float4*>(&Bt[(size_t)(n0 + r + i*32)*K + k0 + c]);
            *reinterpret_cast<float4*>(&Bs[r + i*32][c]) = vb;
        }
        __syncthreads();
#pragma unroll
        for (int kc = 0; kc < 32; kc += 8) {
            uint32_t afb[4][4], afs[4][4], bfb[4][2], bfs[4][2];
            const int cc = kc + (lane & 3);
#pragma unroll
            for (int mt = 0; mt < 4; mt++) {
                int mb = wr*64 + mt*16 + (lane >> 2);
                f2tf2(As[mb][cc],    afb[mt][0], afs[mt][0]);
                f2tf2(As[mb+8][cc],  afb[mt][1], afs[mt][1]);
                f2tf2(As[mb][cc+4],  afb[mt][2], afs[mt][2]);
                f2tf2(As[mb+8][cc+4],afb[mt][3], afs[mt][3]);
            }
#pragma unroll
            for (int nt = 0; nt < 4; nt++) {
                int nb = wc*32 + nt*8 + (lane >> 2);
                f2tf2(Bs[nb][cc],   bfb[nt][0], bfs[nt][0]);
                f2tf2(Bs[nb][cc+4], bfb[nt][1], bfs[nt][1]);
            }
#pragma unroll
            for (int mt = 0; mt < 4; mt++)
#pragma unroll
                for (int nt = 0; nt < 4; nt++) {
                    mma1688(acc[mt][nt], afb[mt], bfs[nt]);
                    mma1688(acc[mt][nt], afs[mt], bfb[nt]);
                    mma1688(acc[mt][nt], afb[mt], bfb[nt]);
                }
        }
        __syncthreads();
    }
#pragma unroll
    for (int mt = 0; mt < 4; mt++) {
        int row = m0 + wr*64 + mt*16 + (lane >> 2);
#pragma unroll
        for (int nt = 0; nt < 4; nt++) {
            int col = n0 + wc*32 + nt*8 + (lane & 3)*2;
            C[(size_t)row*N + col]       = acc[mt][nt][0];
            C[(size_t)row*N + col + 1]   = acc[mt][nt][1];
            C[(size_t)(row+8)*N + col]   = acc[mt][nt][2];
            C[(size_t)(row+8)*N + col+1] = acc[mt][nt][3];
        }
    }
}

// ============ grouped MoE GEMM via 3xTF32 MMA ============
// A=[MOE_ROWS,K] abs-indexed (128-row padded), Ball=[E,K,N] row-major.
__global__ void gemm_moe_mma(const float* __restrict__ A, const float* __restrict__ Ball,
                             float* __restrict__ C, int N, int K) {
    const int e = blockIdx.z;
    const int r0 = g_off[e], r1 = g_off[e+1];
    const int m0 = r0 + blockIdx.y*128;
    if (m0 >= r1) return;
    const float* B = Ball + (size_t)e*K*N;
    __shared__ float As[128][36];   // [m][k]
    __shared__ float Bs[32][132];   // [k][n]
    const int tid = threadIdx.x, lane = tid & 31, warp = tid >> 5;
    const int wr = warp & 1, wc = warp >> 1;
    const int n0 = blockIdx.x*128;
    const int ra = tid >> 3, ca = (tid & 7)*4;        // A loader
    const int kb = tid >> 5, nb4 = (tid & 31)*4;      // B loader
    float acc[4][4][4] = {};

    for (int k0 = 0; k0 < K; k0 += 32) {
#pragma unroll
        for (int i = 0; i < 4; i++) {
            float4 va = *reinterpret_cast<const float4*>(&A[(size_t)(m0 + ra + i*32)*K + k0 + ca]);
            *reinterpret_cast<float4*>(&As[ra + i*32][ca]) = va;   // padded rows: safe
            float4 vb = *reinterpret_cast<const float4*>(&B[(size_t)(k0 + kb + i*8)*N + n0 + nb4]);
            *reinterpret_cast<float4*>(&Bs[kb + i*8][nb4]) = vb;
        }
        __syncthreads();
#pragma unroll
        for (int kc = 0; kc < 32; kc += 8) {
            uint32_t afb[4][4], afs[4][4], bfb[4][2], bfs[4][2];
            const int cc = kc + (lane & 3);
#pragma unroll
            for (int mt = 0; mt < 4; mt++) {
                int mb = wr*64 + mt*16 + (lane >> 2);
                f2tf2(As[mb][cc],    afb[mt][0], afs[mt][0]);
                f2tf2(As[mb+8][cc],  afb[mt][1], afs[mt][1]);
                f2tf2(As[mb][cc+4],  afb[mt][2], afs[mt][2]);
                f2tf2(As[mb+8][cc+4],afb[mt][3], afs[mt][3]);
            }
#pragma unroll
            for (int nt = 0; nt < 4; nt++) {
                int nn = wc*32 + nt*8 + (lane >> 2);
                f2tf2(Bs[cc][nn],   bfb[nt][0], bfs[nt][0]);
                f2tf2(Bs[cc+4][nn], bfb[nt][1], bfs[nt][1]);
            }
#pragma unroll
            for (int mt = 0; mt < 4; mt++)
#pragma unroll
                for (int nt = 0; nt < 4; nt++) {
                    mma1688(acc[mt][nt], afb[mt], bfs[nt]);
                    mma1688(acc[mt][nt], afs[mt], bfb[nt]);
                    mma1688(acc[mt][nt], afb[mt], bfb[nt]);
                }
        }
        __syncthreads();
    }
#pragma unroll
    for (int mt = 0; mt < 4; mt++) {
        int row = m0 + wr*64 + mt*16 + (lane >> 2);
#pragma unroll
        for (int nt = 0; nt < 4; nt++) {
            int col = n0 + wc*32 + nt*8 + (lane & 3)*2;
            if (row < r1) {
                C[(size_t)row*N + col]     = acc[mt][nt][0];
                C[(size_t)row*N + col + 1] = acc[mt][nt][1];
            }
            if (row + 8 < r1) {
                C[(size_t)(row+8)*N + col]   = acc[mt][nt][2];
                C[(size_t)(row+8)*N + col+1] = acc[mt][nt][3];
            }
        }
    }
}

// ---------------- per-head rmsnorm + RoPE (R2 verbatim) ----------------
__global__ void qknorm_rope_k(float* __restrict__ x, const float* __restrict__ w,
                              const int* __restrict__ pos, int nh) {
    int t = blockIdx.x, tid = threadIdx.x;
    int hh = tid >> 6, d = tid & 63;
    __shared__ float sh[NHEAD*HDIM];
    float v = x[(size_t)t*nh*HDIM + tid];
    sh[tid] = v*v; __syncthreads();
    for (int off = 32; off > 0; off >>= 1) { if (d < off) sh[tid] += sh[tid+off]; __syncthreads(); }
    float r = rsqrtf(sh[hh*64]/64.0f + 1e-6f);
    __syncthreads();
    float nv = v * r * w[d];
    sh[tid] = nv; __syncthreads();
    float other = (d < 32) ? -sh[hh*64 + d + 32] : sh[hh*64 + d - 32];
    int i = d & 31;
    double invf = exp(-((double)i/32.0) * 13.815510557964274);  // ln(1e6)
    float ang = (float)((double)pos[t] * invf);
    float sv, cv;
    sincosf(ang, &sv, &cv);
    x[(size_t)t*nh*HDIM + tid] = nv*cv + other*sv;
}

// ---------------- attention (R2 verbatim: 128 threads) ----------------
__global__ void attn_k() {
    const int qpos = blockIdx.x, h = blockIdx.y, b = blockIdx.z;
    const int tid = threadIdx.x;
    const int kvh = h >> 2;                 // GQA: 4 q-heads per kv head
    const int t = b*SEQ + qpos;
    __shared__ float qv[HDIM];
    __shared__ float sc[SEQ];
    __shared__ float red[128];
    if (tid < HDIM) qv[tid] = g_q[(size_t)t*(NHEAD*HDIM) + h*HDIM + tid];
    __syncthreads();
    const int nk = qpos + 1;
    float lm = -1e30f;
    for (int j = tid; j < nk; j += 128) {
        const float* kp = g_k + ((size_t)(b*SEQ + j)*NKV + kvh)*HDIM;
        float s = 0.f;
#pragma unroll
        for (int dd = 0; dd < HDIM; dd++) s += qv[dd]*kp[dd];
        s *= 0.125f;                        // 1/sqrt(64)
        sc[j] = s;
        lm = fmaxf(lm, s);
    }
    red[tid] = lm; __syncthreads();
    for (int off = 64; off > 0; off >>= 1) { if (tid < off) red[tid] = fmaxf(red[tid], red[tid+off]); __syncthreads(); }
    float m = red[0]; __syncthreads();
    float ls = 0.f;
    for (int j = tid; j < nk; j += 128) { float p = __expf(sc[j] - m); sc[j] = p; ls += p; }
    red[tid] = ls; __syncthreads();
    for (int off = 64; off > 0; off >>= 1) { if (tid < off) red[tid] += red[tid+off]; __syncthreads(); }
    float inv = 1.0f / red[0];
    if (tid < HDIM) {
        float acc = 0.f;
        for (int j = 0; j < nk; j++)
            acc += sc[j] * g_v[((size_t)(b*SEQ + j)*NKV + kvh)*HDIM + tid];
        g_ao[(size_t)t*(NHEAD*HDIM) + h*HDIM + tid] = acc * inv;
    }
}

// ---------------- router (R2 verbatim) ----------------
__global__ void router_k(const float* __restrict__ rw) {
    int t = blockIdx.x, tid = threadIdx.x;
    float acc[NEXP] = {};
    for (int d = tid; d < DMODEL; d += 256) {
        float hv = g_h[(size_t)t*DMODEL + d];
        const float* rp = rw + (size_t)d*NEXP;
#pragma unroll
        for (int e = 0; e < NEXP; e++) acc[e] += hv*rp[e];
    }
    __shared__ float red[256];
    __shared__ float logits[NEXP];
    for (int e = 0; e < NEXP; e++) {
        red[tid] = acc[e]; __syncthreads();
        for (int off = 128; off > 0; off >>= 1) { if (tid < off) red[tid] += red[tid+off]; __syncthreads(); }
        if (tid == 0) logits[e] = red[0];
        __syncthreads();
    }
    if (tid == 0) {
        float mx = logits[0];
        for (int e = 1; e < NEXP; e++) mx = fmaxf(mx, logits[e]);
        float p[NEXP];
        for (int e = 0; e < NEXP; e++) p[e] = expf(logits[e] - mx);
        int i0 = 0;
        for (int e = 1; e < NEXP; e++) if (p[e] > p[i0]) i0 = e;   // ties -> lowest idx
        int i1 = (i0 == 0) ? 1 : 0;
        for (int e = 0; e < NEXP; e++) if (e != i0 && p[e] > p[i1]) i1 = e;
        float v0 = p[i0], v1 = p[i1], tt = v0 + v1;
        g_topi[t*2] = i0;  g_topi[t*2+1] = i1;
        g_gate[t*2] = v0/tt; g_gate[t*2+1] = v1/tt;
    }
}

// ---------------- routing bookkeeping (R2 verbatim) ----------------
__global__ void route_zero_k()   { if (threadIdx.x < NEXP) g_cnt[threadIdx.x] = 0; }
__global__ void route_count_k()  { int i = blockIdx.x*256 + threadIdx.x; if (i < 2*T) atomicAdd(&g_cnt[g_topi[i]], 1); }
__global__ void route_prefix_k() {
    if (threadIdx.x == 0) {
        int s = 0;
        for (int e = 0; e < NEXP; e++) { g_off[e] = s; g_cur[e] = s; s += g_cnt[e]; }
        g_off[NEXP] = s;
    }
}
__global__ void route_assign_k() {
    int i = blockIdx.x*256 + threadIdx.x;
    if (i < 2*T) {
        int e = g_topi[i];
        int pos = atomicAdd(&g_cur[e], 1);
        g_ptok[pos] = i >> 1;
        g_rowof[i] = pos;
    }
}
__global__ void moe_gather_k() {
    int i = blockIdx.x;
    int tk = g_ptok[i];
    for (int d = threadIdx.x; d < DMODEL; d += 256)
        g_hg[(size_t)i*DMODEL + d] = g_h[(size_t)tk*DMODEL + d];
}
__global__ void moe_act_k() {
    size_t i = (size_t)blockIdx.x*256 + threadIdx.x;   // grid covers 2*T*FDIM
    float g = g_gb[i], u = g_ub[i];
    float sg = g / (1.0f + expf(-g));
    g_gb[i] = sg * u;
}
__global__ void moe_combine_k() {
    int t = blockIdx.x;
    int r0 = g_rowof[t*2], r1 = g_rowof[t*2+1];
    float w0 = g_gate[t*2], w1 = g_gate[t*2+1];
    for (int d = threadIdx.x; d < DMODEL; d += 256)
        g_x[(size_t)t*DMODEL + d] += w0*g_yb[(size_t)r0*DMODEL + d]
                                   + w1*g_yb[(size_t)r1*DMODEL + d];
}

// ---------------- host orchestration ----------------
extern "C" void kernel_launch(void* const* d_in, const int* in_sizes, int n_in,
                              void* d_out, int out_size) {
    const int*   token_ids    = (const int*)  d_in[0];
    const int*   position_ids = (const int*)  d_in[1];
    const float* tok_emb      = (const float*)d_in[2];
    const float* attn_norm_w  = (const float*)d_in[3];
    const float* wq           = (const float*)d_in[4];
    const float* wk           = (const float*)d_in[5];
    const float* wv           = (const float*)d_in[6];
    const float* q_norm_w     = (const float*)d_in[7];
    const float* k_norm_w     = (const float*)d_in[8];
    const float* wo           = (const float*)d_in[9];
    const float* ffn_norm_w   = (const float*)d_in[10];
    const float* router_w     = (const float*)d_in[11];
    const float* gate_w       = (const float*)d_in[12];
    const float* up_w         = (const float*)d_in[13];
    const float* down_w       = (const float*)d_in[14];
    const float* final_norm_w = (const float*)d_in[15];
    float* out = (float*)d_out;

    float* px; cudaGetSymbolAddress((void**)&px, g_x);
    float* ph; cudaGetSymbolAddress((void**)&ph, g_h);
    float* pq; cudaGetSymbolAddress((void**)&pq, g_q);
    float* pk; cudaGetSymbolAddress((void**)&pk, g_k);
    float* pv; cudaGetSymbolAddress((void**)&pv, g_v);
    float* pao; cudaGetSymbolAddress((void**)&pao, g_ao);
    float* phg; cudaGetSymbolAddress((void**)&phg, g_hg);
    float* pgb; cudaGetSymbolAddress((void**)&pgb, g_gb);
    float* pub; cudaGetSymbolAddress((void**)&pub, g_ub);
    float* pyb; cudaGetSymbolAddress((void**)&pyb, g_yb);

    embed_k<<<T, 256>>>(token_ids, tok_emb);

    for (int l = 0; l < NLAYER; l++) {
        const float* wq_l = wq + (size_t)l*DMODEL*(NHEAD*HDIM);
        const float* wk_l = wk + (size_t)l*DMODEL*(NKV*HDIM);
        const float* wv_l = wv + (size_t)l*DMODEL*(NKV*HDIM);
        const float* wo_l = wo + (size_t)l*(NHEAD*HDIM)*DMODEL;
        const float* gw_l = gate_w + (size_t)l*NEXP*DMODEL*FDIM;
        const float* uw_l = up_w   + (size_t)l*NEXP*DMODEL*FDIM;
        const float* dw_l = down_w + (size_t)l*NEXP*FDIM*DMODEL;

        // attention block (R2 verbatim)
        rmsnorm_k<<<T, 256>>>(px, attn_norm_w + (size_t)l*DMODEL, ph);
        sgemm_nn<<<dim3((NHEAD*HDIM)/BN, T/BM), 256>>>(ph, wq_l, pq, nullptr, T, NHEAD*HDIM, DMODEL);
        sgemm_nn<<<dim3((NKV*HDIM)/BN,  T/BM), 256>>>(ph, wk_l, pk, nullptr, T, NKV*HDIM, DMODEL);
        sgemm_nn<<<dim3((NKV*HDIM)/BN,  T/BM), 256>>>(ph, wv_l, pv, nullptr, T, NKV*HDIM, DMODEL);
        qknorm_rope_k<<<T, NHEAD*HDIM>>>(pq, q_norm_w + (size_t)l*HDIM, position_ids, NHEAD);
        qknorm_rope_k<<<T, NKV*HDIM>>>(pk, k_norm_w + (size_t)l*HDIM, position_ids, NKV);
        attn_k<<<dim3(SEQ, NHEAD, BATCH), 128>>>();
        sgemm_nn<<<dim3(DMODEL/BN, T/BM), 256>>>(pao, wo_l, px, px, T, DMODEL, NHEAD*HDIM);

        // MoE block — grouped GEMMs via 3xTF32 MMA
        rmsnorm_k<<<T, 256>>>(px, ffn_norm_w + (size_t)l*DMODEL, ph);
        router_k<<<T, 256>>>(router_w + (size_t)l*DMODEL*NEXP);
        route_zero_k<<<1, 32>>>();
        route_count_k<<<(2*T)/256, 256>>>();
        route_prefix_k<<<1, 32>>>();
        route_assign_k<<<(2*T)/256, 256>>>();
        moe_gather_k<<<2*T, 256>>>();
        gemm_moe_mma<<<dim3(FDIM/128, (2*T)/128, NEXP), 256>>>(phg, gw_l, pgb, FDIM, DMODEL);
        gemm_moe_mma<<<dim3(FDIM/128, (2*T)/128, NEXP), 256>>>(phg, uw_l, pub, FDIM, DMODEL);
        moe_act_k<<<(2*T*FDIM)/256, 256>>>();
        gemm_moe_mma<<<dim3(DMODEL/128, (2*T)/128, NEXP), 256>>>(pgb, dw_l, pyb, DMODEL, FDIM);
        moe_combine_k<<<T, 256>>>();
    }

    // final norm + tied lm_head — 3xTF32 MMA
    rmsnorm_k<<<T, 256>>>(px, final_norm_w, ph);
    gemm_nt_mma<<<dim3(VOCAB/128, T/128), 256>>>(ph, tok_emb, out, T, VOCAB, DMODEL);
}